// round 1
// baseline (speedup 1.0000x reference)
#include <cuda_runtime.h>
#include <cuda_bf16.h>
#include <cstdint>

// dense_baens: out[n, e] = sum_d x[n, d] * U[n, d, e] + bias[n, 0, e]
// N=2048, D1=512, D2=512, all float32.
//
// HBM-bound streaming kernel: U (2.147 GB) is read exactly once.
// One CTA per sample; 128 threads; each thread owns a float4 column group.

#define BN 2048
#define BD1 512
#define BD2 512

__global__ __launch_bounds__(128, 8)
void dense_baens_kernel(const float* __restrict__ x,
                        const float* __restrict__ U,
                        const float* __restrict__ bias,
                        float* __restrict__ out)
{
    const int n = blockIdx.x;
    const int t = threadIdx.x;  // 0..127, column group index (4 cols each)

    __shared__ float xs[BD1];

    // Stage x[n, :] into shared (2 KB), coalesced.
    const float* xrow = x + (size_t)n * BD1;
    #pragma unroll
    for (int i = 0; i < BD1 / 128; i++) {
        xs[t + i * 128] = xrow[t + i * 128];
    }
    __syncthreads();

    // U[n] base as float4 rows of width 128.
    const float4* __restrict__ Un =
        reinterpret_cast<const float4*>(U + (size_t)n * BD1 * BD2) + t;

    float4 acc = make_float4(0.f, 0.f, 0.f, 0.f);

    // d-loop: per iteration the CTA streams one contiguous 2 KB row of U.
    // Unroll 8 -> 8 outstanding LDG.128 per thread (MLP=8).
    #pragma unroll 8
    for (int d = 0; d < BD1; d++) {
        const float4 u = Un[(size_t)d * (BD2 / 4)];
        const float xv = xs[d];
        acc.x = fmaf(xv, u.x, acc.x);
        acc.y = fmaf(xv, u.y, acc.y);
        acc.z = fmaf(xv, u.z, acc.z);
        acc.w = fmaf(xv, u.w, acc.w);
    }

    // bias is (N, 1, D2) contiguous => bias[n * D2 + e]
    const float4 b =
        reinterpret_cast<const float4*>(bias + (size_t)n * BD2)[t];
    acc.x += b.x; acc.y += b.y; acc.z += b.z; acc.w += b.w;

    reinterpret_cast<float4*>(out + (size_t)n * BD2)[t] = acc;
}

extern "C" void kernel_launch(void* const* d_in, const int* in_sizes, int n_in,
                              void* d_out, int out_size)
{
    const float* x    = (const float*)d_in[0];   // (2048, 512)
    const float* U    = (const float*)d_in[1];   // (2048, 512, 512)
    const float* bias = (const float*)d_in[2];   // (2048, 1, 512)
    float* out        = (float*)d_out;           // (2048, 512)

    dense_baens_kernel<<<BN, 128>>>(x, U, bias, out);
}

// round 2
// speedup vs baseline: 1.0212x; 1.0212x over previous
#include <cuda_runtime.h>
#include <cuda_bf16.h>
#include <cstdint>

// dense_baens: out[n, e] = sum_d x[n, d] * U[n, d, e] + bias[n, 0, e]
// N=2048, D1=512, D2=512, all float32.
//
// Pure HBM-streaming kernel: U (2.147 GB) read once, zero reuse.
// R2: grid=1024 (2 samples per CTA) -> single wave on 148 SMs @ occ 8,
//     no wave-2 underutilization; evict-first streaming loads for U.

#define BN 2048
#define BD1 512
#define BD2 512
#define SAMPLES_PER_CTA 2
#define GRID (BN / SAMPLES_PER_CTA)

__global__ __launch_bounds__(128, 8)
void dense_baens_kernel(const float* __restrict__ x,
                        const float* __restrict__ U,
                        const float* __restrict__ bias,
                        float* __restrict__ out)
{
    const int t = threadIdx.x;  // 0..127, column group index (4 cols each)

    __shared__ float xs[SAMPLES_PER_CTA][BD1];

    // Stage x rows for both samples (4 KB), coalesced.
    #pragma unroll
    for (int s = 0; s < SAMPLES_PER_CTA; s++) {
        const int n = blockIdx.x + s * GRID;
        const float* xrow = x + (size_t)n * BD1;
        #pragma unroll
        for (int i = 0; i < BD1 / 128; i++) {
            xs[s][t + i * 128] = xrow[t + i * 128];
        }
    }
    __syncthreads();

    #pragma unroll 1
    for (int s = 0; s < SAMPLES_PER_CTA; s++) {
        const int n = blockIdx.x + s * GRID;

        // U[n] base as float4 rows of width 128.
        const float4* __restrict__ Un =
            reinterpret_cast<const float4*>(U + (size_t)n * BD1 * BD2) + t;

        float4 acc = make_float4(0.f, 0.f, 0.f, 0.f);

        // Per iteration the CTA streams one contiguous 2 KB row of U.
        // Unroll 8 -> 8 outstanding LDG.128 per thread (MLP=8).
        // Evict-first streaming: U has zero reuse, don't pollute L2.
        #pragma unroll 8
        for (int d = 0; d < BD1; d++) {
            const float4 u = __ldcs(Un + (size_t)d * (BD2 / 4));
            const float xv = xs[s][d];
            acc.x = fmaf(xv, u.x, acc.x);
            acc.y = fmaf(xv, u.y, acc.y);
            acc.z = fmaf(xv, u.z, acc.z);
            acc.w = fmaf(xv, u.w, acc.w);
        }

        // bias is (N, 1, D2) contiguous => bias[n * D2 + e]
        const float4 b =
            reinterpret_cast<const float4*>(bias + (size_t)n * BD2)[t];
        acc.x += b.x; acc.y += b.y; acc.z += b.z; acc.w += b.w;

        __stcs(reinterpret_cast<float4*>(out + (size_t)n * BD2) + t, acc);
    }
}

extern "C" void kernel_launch(void* const* d_in, const int* in_sizes, int n_in,
                              void* d_out, int out_size)
{
    const float* x    = (const float*)d_in[0];   // (2048, 512)
    const float* U    = (const float*)d_in[1];   // (2048, 512, 512)
    const float* bias = (const float*)d_in[2];   // (2048, 1, 512)
    float* out        = (float*)d_out;           // (2048, 512)

    dense_baens_kernel<<<GRID, 128>>>(x, U, bias, out);
}